// round 17
// baseline (speedup 1.0000x reference)
#include <cuda_runtime.h>
#include <cstdint>

#define E_NUM 60000
#define LDX   3712          // 29 * 128, row stride of x and out
#define M16_PAD 3752        // 60032 / 16 (padded row blocks)

// fragment-order scratch (static device globals: allowed)
// A: per slice, record (m16, kt, ks) = [lane][float4] with
//   float4 = (A[r][k], A[r+8][k], A[r][k+4], A[r+8][k+4]),
//   r = m16*16 + lane>>2, k = kt*32 + ks*8 + (lane&3)
// total float4 records = 3752 * (28+48+40) * 128
__device__ float4 g_xf[(size_t)M16_PAD * 116 * 128];
// B (weights): layout [kt][jb][g][lane] float4  (R15 layout)
__device__ float g_w0f[896 * 896];
__device__ float g_w1f[1536 * 1536];
__device__ float g_w2f[1280 * 1280];

__device__ __forceinline__ float to_tf32(float x) {
    uint32_t u;
    asm("cvt.rna.tf32.f32 %0, %1;" : "=r"(u) : "f"(x));
    return __uint_as_float(u);
}

// ---------------- A prep: fragment-order, rna-rounded, zero-padded ----------------
// record index i (within slice): lane = i&31, ks = (i>>5)&3, rest = i>>7,
// kt = rest % KT, m16 = rest / KT.
__global__ void prep_xf_k(const float* __restrict__ x, int off, int KT,
                          long long base, int nrec)
{
    int i = blockIdx.x * blockDim.x + threadIdx.x;
    if (i >= nrec) return;
    int lane = i & 31;
    int ks   = (i >> 5) & 3;
    int rest = i >> 7;
    int kt   = rest % KT;
    int m16  = rest / KT;
    int r0 = m16 * 16 + (lane >> 2);
    int k0 = kt * 32 + ks * 8 + (lane & 3);
    float4 v;
    if (m16 < E_NUM / 16) {      // rows m16*16 .. +15 all valid
        const float* p = x + (size_t)r0 * LDX + off + k0;
        v.x = to_tf32(p[0]);
        v.y = to_tf32(p[(size_t)8 * LDX]);
        v.z = to_tf32(p[4]);
        v.w = to_tf32(p[(size_t)8 * LDX + 4]);
    } else {
        v = make_float4(0.f, 0.f, 0.f, 0.f);
    }
    g_xf[base + i] = v;
}

// ---------------- weight prep: fragment-order, rna-rounded (R15) ----------------

__global__ void prep_w0f_k(const float* __restrict__ src) {
    int i = blockIdx.x * blockDim.x + threadIdx.x;
    if (i >= 896 * 896) return;
    const int NB = 896 / 8;
    int q = i & 3, lane = (i >> 2) & 31, g = (i >> 7) & 1;
    int rest = i >> 8;
    int jb = rest % NB, kt = rest / NB;
    int k = kt * 32 + (g * 2 + (q >> 1)) * 8 + (q & 1) * 4 + (lane & 3);
    int n = jb * 8 + (lane >> 2);
    g_w0f[i] = to_tf32(src[k * 896 + n]);
}
__global__ void prep_so2f_k(const float* __restrict__ src, int H, int which) {
    float* dst = (which == 1) ? g_w1f : g_w2f;
    const int W2 = 2 * H;
    const int NB = W2 / 8;
    int i = blockIdx.x * blockDim.x + threadIdx.x;
    if (i >= W2 * W2) return;
    int q = i & 3, lane = (i >> 2) & 31, g = (i >> 7) & 1;
    int rest = i >> 8;
    int jb = rest % NB, kt = rest / NB;
    int k = kt * 32 + (g * 2 + (q >> 1)) * 8 + (q & 1) * 4 + (lane & 3);
    int n = jb * 8 + (lane >> 2);
    float v;
    if (k < H) {
        v = src[k * W2 + n];
    } else {
        int kk = k - H;
        v = (n < H) ? -src[kk * W2 + n + H] : src[kk * W2 + n - H];
    }
    dst[i] = to_tf32(v);
}

// ---------------- GEMM: zero-smem, zero-barrier ----------------
// Block 128x128xK, 128 threads (4 warps), warp grid 2x2, warp tile 64x64.
// 2 CTAs/SM. A and B fragments both LDG.128 from fragment-order gmem.
// A double-buffered one kstep ahead (A0/A1); B pair-buffered (B0/B1, R15).
// No shared memory, no synchronization of any kind in the mainloop.

__global__ __launch_bounds__(128, 2) void gemm_tf32_k(
    const float4* __restrict__ Af, const float4* __restrict__ Bp,
    const float* __restrict__ bias, float* __restrict__ C,
    int N, int KT)
{
    const int tid  = threadIdx.x;
    const int lane = tid & 31;
    const int warp = tid >> 5;         // 0..3
    const int wm   = warp >> 1;        // 0..1  (64-row strip)
    const int wn   = warp & 1;         // 0..1  (64-col strip)
    const int bn   = blockIdx.x;
    const int bm   = blockIdx.y;

    const int lr = lane >> 2;          // 0..7
    const int lc = lane & 3;           // 0..3

    const int NB = N >> 3;
    const int jbase = bn * 16 + wn * 8;

    // A record base (float4 index): m16 = bm*8 + wm*4 + im
    const uint32_t mstride = (uint32_t)KT * 128u;     // per m16 block
    const uint32_t aBase = (uint32_t)(bm * 8 + wm * 4) * mstride + (uint32_t)lane;

    float acc[4][8][4];
#pragma unroll
    for (int a = 0; a < 4; a++)
#pragma unroll
        for (int b = 0; b < 8; b++)
#pragma unroll
            for (int c = 0; c < 4; c++) acc[a][b][c] = 0.f;

    float4 A0[4], A1[4];               // kstep double buffer
    float4 B0[8], B1[8];               // kstep-pair buffers

    auto ldgA = [&](int kt, int ks, float4* dst) {
        uint32_t idx = aBase + (uint32_t)kt * 128u + (uint32_t)ks * 32u;
#pragma unroll
        for (int im = 0; im < 4; im++)
            dst[im] = Af[idx + (uint32_t)im * mstride];
    };
    auto ldgB = [&](int kt, int g, float4* dst) {
#pragma unroll
        for (int jn = 0; jn < 8; jn++)
            dst[jn] = Bp[((size_t)kt * NB + jbase + jn) * 64 + g * 32 + lane];
    };

    // 32 MMAs of one kstep; Av = A fragments, Bv = pair buffer, hi = odd kstep
    auto mma_ks = [&](const float4* Av, const float4* Bv, int hi) {
#pragma unroll
        for (int im = 0; im < 4; im++) {
            uint32_t a0 = __float_as_uint(Av[im].x);
            uint32_t a1 = __float_as_uint(Av[im].y);
            uint32_t a2 = __float_as_uint(Av[im].z);
            uint32_t a3 = __float_as_uint(Av[im].w);
#pragma unroll
            for (int jn = 0; jn < 8; jn++) {
                uint32_t b0 = __float_as_uint(hi ? Bv[jn].z : Bv[jn].x);
                uint32_t b1 = __float_as_uint(hi ? Bv[jn].w : Bv[jn].y);
                asm volatile(
                    "mma.sync.aligned.m16n8k8.row.col.f32.tf32.tf32.f32 "
                    "{%0,%1,%2,%3}, {%4,%5,%6,%7}, {%8,%9}, {%0,%1,%2,%3};\n"
                    : "+f"(acc[im][jn][0]), "+f"(acc[im][jn][1]),
                      "+f"(acc[im][jn][2]), "+f"(acc[im][jn][3])
                    : "r"(a0), "r"(a1), "r"(a2), "r"(a3),
                      "r"(b0), "r"(b1));
            }
        }
    };

    // prologue
    ldgA(0, 0, A0);
    ldgB(0, 0, B0);
    ldgB(0, 1, B1);

    for (int kt = 0; kt < KT; kt++) {
        const bool nxt = (kt + 1 < KT);
        ldgA(kt, 1, A1);  mma_ks(A0, B0, 0);          // ks0
        ldgA(kt, 2, A0);  mma_ks(A1, B0, 1);          // ks1
        if (nxt) ldgB(kt + 1, 0, B0);                 // B0 dead
        ldgA(kt, 3, A1);  mma_ks(A0, B1, 0);          // ks2
        if (nxt) ldgA(kt + 1, 0, A0);
        mma_ks(A1, B1, 1);                            // ks3
        if (nxt) ldgB(kt + 1, 1, B1);                 // B1 dead
    }

    // epilogue
#pragma unroll
    for (int im = 0; im < 4; im++) {
        int r0 = bm * 128 + wm * 64 + im * 16 + lr;
#pragma unroll
        for (int jn = 0; jn < 8; jn++) {
            int cg = bn * 128 + wn * 64 + jn * 8 + lc * 2;
            float bv0 = 0.f, bv1 = 0.f;
            if (bias) { bv0 = bias[cg]; bv1 = bias[cg + 1]; }
            if (r0 < E_NUM) {
                float2 v; v.x = acc[im][jn][0] + bv0; v.y = acc[im][jn][1] + bv1;
                *reinterpret_cast<float2*>(C + (size_t)r0 * LDX + cg) = v;
            }
            if (r0 + 8 < E_NUM) {
                float2 v; v.x = acc[im][jn][2] + bv0; v.y = acc[im][jn][3] + bv1;
                *reinterpret_cast<float2*>(C + (size_t)(r0 + 8) * LDX + cg) = v;
            }
        }
    }
}

// ---------------- launch ----------------

extern "C" void kernel_launch(void* const* d_in, const int* in_sizes, int n_in,
                              void* d_out, int out_size)
{
    const float* x  = (const float*)d_in[0];
    // d_in[1] = x_edge: unused by the reference
    const float* w0 = (const float*)d_in[2];
    const float* b0 = (const float*)d_in[3];
    const float* w1 = (const float*)d_in[4];
    const float* w2 = (const float*)d_in[5];
    float* out = (float*)d_out;

    // weight preps
    prep_w0f_k<<<(896 * 896 + 255) / 256, 256>>>(w0);
    prep_so2f_k<<<(1536 * 1536 + 255) / 256, 256>>>(w1, 768, 1);
    prep_so2f_k<<<(1280 * 1280 + 255) / 256, 256>>>(w2, 640, 2);

    // A preps (slice record counts; bases in float4 records)
    const int  nr0 = M16_PAD * 28 * 128;               // 13,447,168
    const int  nr1 = M16_PAD * 48 * 128;               // 23,052,288
    const int  nr2 = M16_PAD * 40 * 128;               // 19,210,240
    const long long b0f = 0;
    const long long b1f = (long long)nr0;
    const long long b2f = (long long)nr0 + nr1;
    prep_xf_k<<<(nr0 + 255) / 256, 256>>>(x, 0,    28, b0f, nr0);
    prep_xf_k<<<(nr1 + 255) / 256, 256>>>(x, 896,  48, b1f, nr1);
    prep_xf_k<<<(nr2 + 255) / 256, 256>>>(x, 2432, 40, b2f, nr2);

    float4* xf;
    float *pw0, *pw1, *pw2;
    cudaGetSymbolAddress((void**)&xf,  g_xf);
    cudaGetSymbolAddress((void**)&pw0, g_w0f);
    cudaGetSymbolAddress((void**)&pw1, g_w1f);
    cudaGetSymbolAddress((void**)&pw2, g_w2f);

    const int mb = (E_NUM + 127) / 128;   // 469
    // m=0: (E,896) @ (896,896) + bias  -> out cols 0..895
    gemm_tf32_k<<<dim3(7, mb), 128>>>(xf + b0f, (const float4*)pw0, b0,
                                      out,        896,  28);
    // m=1: (E,1536) @ (1536,1536)      -> out cols 896..2431
    gemm_tf32_k<<<dim3(12, mb), 128>>>(xf + b1f, (const float4*)pw1, nullptr,
                                       out + 896,  1536, 48);
    // m=2: (E,1280) @ (1280,1280)      -> out cols 2432..3711
    gemm_tf32_k<<<dim3(10, mb), 128>>>(xf + b2f, (const float4*)pw2, nullptr,
                                       out + 2432, 1280, 40);
}